// round 3
// baseline (speedup 1.0000x reference)
#include <cuda_runtime.h>
#include <cstdint>

#define NB    4096     // batch
#define NO    256      // orbitals
#define NF    128      // fermions
#define HID   512      // hidden
#define LDA   129      // padded row stride (129 mod 32 == 1 -> conflict-free columns)
#define NTHR  256

// Shared layout (floats):
//  A:     NF*LDA            = 16512
//  idx:   NF ints
//  perm:  NF ints
//  redv:  8 floats, redi: 8 ints, wcnt: 8 ints, sJ: 8 floats, scal: 4
#define SMEM_FLOATS (NF*LDA + NF + NF + 8 + 8 + 8 + 8 + 4)
#define SMEM_BYTES  (SMEM_FLOATS * 4)

__global__ void __launch_bounds__(NTHR)
lnjs_kernel(const float* __restrict__ n_in,
            const float* __restrict__ M_in,
            const float* __restrict__ W_in,
            const float* __restrict__ b_in,
            float* __restrict__ out)
{
    extern __shared__ float sm[];
    float* A    = sm;
    int*   idx  = (int*)(sm + NF*LDA);
    int*   perm = idx + NF;
    float* redv = (float*)(perm + NF);
    int*   redi = (int*)(redv + 8);
    int*   wcnt = redi + 8;
    float* sJ   = (float*)(wcnt + 8);
    float* scal = sJ + 8;                 // scal[0]=inv_piv, ((int*)scal)[1]=pk

    const int s    = blockIdx.x;
    const int tid  = threadIdx.x;
    const int lane = tid & 31;
    const int wid  = tid >> 5;

    // ---------- 1. occupied indices via ballot prefix (NO == NTHR == 256) ----------
    const float nv = n_in[s*NO + tid];
    const bool occ = nv > 0.5f;
    const unsigned mask = __ballot_sync(0xffffffffu, occ);
    const int rank = __popc(mask & ((1u << lane) - 1u));
    if (lane == 0) wcnt[wid] = __popc(mask);
    __syncthreads();
    {
        int off = 0;
        #pragma unroll
        for (int w = 0; w < 8; w++) if (w < wid) off += wcnt[w];
        if (occ) idx[off + rank] = tid;
    }
    if (tid < NF) perm[tid] = tid;
    __syncthreads();

    // ---------- 2. Jastrow: each thread owns columns tid and tid+256 ----------
    float acc0 = b_in[tid];
    float acc1 = b_in[tid + 256];
    #pragma unroll 4
    for (int i = 0; i < NF; i++) {
        const float* wr = W_in + (size_t)idx[i] * HID;   // idx broadcast from smem
        acc0 += wr[tid];
        acc1 += wr[tid + 256];
    }
    float jl = tanhf(acc0) + tanhf(acc1);
    #pragma unroll
    for (int o = 16; o; o >>= 1) jl += __shfl_xor_sync(0xffffffffu, jl, o);
    if (lane == 0) sJ[wid] = jl;
    // (no sync needed yet; the A-load sync below covers sJ)

    // ---------- 3. load Slater matrix A = M[idx] into smem ----------
    #pragma unroll
    for (int e = tid; e < NF*NF; e += NTHR) {
        const int r = e >> 7;
        const int c = e & 127;
        A[r*LDA + c] = M_in[(size_t)idx[r] * NF + c];
    }
    __syncthreads();

    // ---------- 4. LU with partial pivoting (virtual row swaps via perm) ----------
    float logabs = 0.0f;   // accumulated by thread 0 only

    for (int k = 0; k < NF; k++) {
        // pivot search over logical rows i in [k,128): warps 0..3
        float v  = -1.0f;
        int   vi = k;
        if (tid < NF && tid >= k) {
            v  = fabsf(A[perm[tid]*LDA + k]);
            vi = tid;
        }
        #pragma unroll
        for (int o = 16; o; o >>= 1) {
            float ov = __shfl_xor_sync(0xffffffffu, v,  o);
            int   oi = __shfl_xor_sync(0xffffffffu, vi, o);
            if (ov > v) { v = ov; vi = oi; }
        }
        if (lane == 0) { redv[wid] = v; redi[wid] = vi; }
        __syncthreads();

        if (tid == 0) {
            float bv = -1.0f; int bi = k;
            #pragma unroll
            for (int w = 0; w < 4; w++) if (redv[w] > bv) { bv = redv[w]; bi = redi[w]; }
            if (bi != k) { int t = perm[k]; perm[k] = perm[bi]; perm[bi] = t; }
            const int pk = perm[k];
            const float piv = A[pk*LDA + k];
            logabs += logf(fabsf(piv));
            scal[0] = 1.0f / piv;
            ((int*)scal)[1] = pk;
        }
        __syncthreads();

        const float inv = scal[0];
        const int   pk  = ((int*)scal)[1];

        // cache pivot row (lane-strided) in registers; only columns > k matter
        const float* prow = A + pk*LDA;
        const float p0 = prow[lane];
        const float p1 = prow[lane + 32];
        const float p2 = prow[lane + 64];
        const float p3 = prow[lane + 96];

        // trailing rank-1 update: 8 warps round-robin over logical rows > k
        for (int i = k + 1 + wid; i < NF; i += 8) {
            const int pi = perm[i];                 // broadcast LDS
            float* row = A + pi*LDA;
            const float m = row[k] * inv;           // broadcast LDS
            if (lane      > k) row[lane     ] -= m * p0;
            if (lane + 32 > k) row[lane + 32] -= m * p1;
            if (lane + 64 > k) row[lane + 64] -= m * p2;
            if (lane + 96 > k) row[lane + 96] -= m * p3;
        }
        __syncthreads();
    }

    // ---------- 5. combine & write REAL part of log psi (float32 output) ----------
    if (tid == 0) {
        float J = 0.0f;
        #pragma unroll
        for (int w = 0; w < 8; w++) J += sJ[w];
        out[s] = logabs + J;
    }
}

extern "C" void kernel_launch(void* const* d_in, const int* in_sizes, int n_in,
                              void* d_out, int out_size)
{
    // Identify inputs by element count (robust to metadata ordering):
    //   n: 4096*256 = 1048576,  M: 256*128 = 32768,
    //   W: 256*512 = 131072,    b: 512
    const float* n = nullptr;
    const float* M = nullptr;
    const float* W = nullptr;
    const float* b = nullptr;
    for (int i = 0; i < n_in; i++) {
        switch (in_sizes[i]) {
            case NB * NO:  n = (const float*)d_in[i]; break;
            case NO * NF:  M = (const float*)d_in[i]; break;
            case NO * HID: W = (const float*)d_in[i]; break;
            case HID:      b = (const float*)d_in[i]; break;
            default: break;
        }
    }
    float* out = (float*)d_out;   // (4096,) float32: real part of log psi

    cudaFuncSetAttribute(lnjs_kernel,
                         cudaFuncAttributeMaxDynamicSharedMemorySize,
                         SMEM_BYTES);

    lnjs_kernel<<<NB, NTHR, SMEM_BYTES>>>(n, M, W, b, out);
}

// round 5
// speedup vs baseline: 1.3610x; 1.3610x over previous
#include <cuda_runtime.h>
#include <cstdint>

#define NB    4096     // batch
#define NO    256      // orbitals
#define NF    128      // fermions
#define HID   512      // hidden
#define LDA   129      // padded row stride (129 mod 32 == 1)
#define NTHR  256
#define PB    8        // LU panel width
#define NPAN  (NF/PB)  // 16 panels

// Shared layout (floats): A (NF*LDA) | idx (NF int) | perm (NF int) | wcnt(8 int) | sJ(8)
#define SMEM_FLOATS (NF*LDA + NF + NF + 8 + 8)
#define SMEM_BYTES  (SMEM_FLOATS * 4)

__global__ void __launch_bounds__(NTHR)
lnjs_kernel(const float* __restrict__ n_in,
            const float* __restrict__ M_in,
            const float* __restrict__ W_in,
            const float* __restrict__ b_in,
            float* __restrict__ out)
{
    extern __shared__ float sm[];
    float* A    = sm;
    int*   idx  = (int*)(sm + NF*LDA);
    int*   perm = idx + NF;
    int*   wcnt = perm + NF;
    float* sJ   = (float*)(wcnt + 8);

    const int s    = blockIdx.x;
    const int tid  = threadIdx.x;
    const int lane = tid & 31;
    const int wid  = tid >> 5;

    // ---------- 1. occupied indices via ballot prefix (NO == NTHR == 256) ----------
    const float nv = n_in[s*NO + tid];
    const bool occ = nv > 0.5f;
    const unsigned mask = __ballot_sync(0xffffffffu, occ);
    const int rank = __popc(mask & ((1u << lane) - 1u));
    if (lane == 0) wcnt[wid] = __popc(mask);
    __syncthreads();
    {
        int off = 0;
        #pragma unroll
        for (int w = 0; w < 8; w++) if (w < wid) off += wcnt[w];
        if (occ) idx[off + rank] = tid;
    }
    if (tid < NF) perm[tid] = tid;
    __syncthreads();

    // ---------- 2. Jastrow: each thread owns hidden units tid and tid+256 ----------
    float acc0 = b_in[tid];
    float acc1 = b_in[tid + 256];
    #pragma unroll 4
    for (int i = 0; i < NF; i++) {
        const float* wr = W_in + (size_t)idx[i] * HID;
        acc0 += wr[tid];
        acc1 += wr[tid + 256];
    }
    float jl = tanhf(acc0) + tanhf(acc1);
    #pragma unroll
    for (int o = 16; o; o >>= 1) jl += __shfl_xor_sync(0xffffffffu, jl, o);
    if (lane == 0) sJ[wid] = jl;

    // ---------- 3. load Slater matrix A = M[idx] into smem ----------
    #pragma unroll
    for (int e = tid; e < NF*NF; e += NTHR) {
        const int r = e >> 7;
        const int c = e & 127;
        A[r*LDA + c] = M_in[(size_t)idx[r] * NF + c];
    }
    __syncthreads();

    // ---------- 4. blocked LU with partial pivoting (virtual swaps via perm) ----------
    float logabs = 0.0f;   // warp 0 lane 0 accumulates

    for (int p = 0; p < NPAN; p++) {
        const int kp = p * PB;

        // ---- panel factorization: warp 0 only, warp-synchronous ----
        if (wid == 0) {
            #pragma unroll
            for (int kk = 0; kk < PB; kk++) {
                const int k = kp + kk;
                // pivot search over logical rows >= k
                float v = -1.0f; int vi = k;
                #pragma unroll
                for (int j = 0; j < 4; j++) {
                    const int i = lane + 32*j;
                    if (i >= k) {
                        const float a = fabsf(A[perm[i]*LDA + k]);
                        if (a > v) { v = a; vi = i; }
                    }
                }
                #pragma unroll
                for (int o = 16; o; o >>= 1) {
                    const float ov = __shfl_xor_sync(0xffffffffu, v,  o);
                    const int   oi = __shfl_xor_sync(0xffffffffu, vi, o);
                    if (ov > v) { v = ov; vi = oi; }
                }
                int pk = 0; float inv = 0.0f;
                if (lane == 0) {
                    if (vi != k) { int t = perm[k]; perm[k] = perm[vi]; perm[vi] = t; }
                    pk = perm[k];
                    const float piv = A[pk*LDA + k];
                    logabs += logf(fabsf(piv));
                    inv = 1.0f / piv;
                }
                __syncwarp();
                pk  = __shfl_sync(0xffffffffu, pk,  0);
                inv = __shfl_sync(0xffffffffu, inv, 0);

                const float* prow = A + pk*LDA + kp;
                #pragma unroll
                for (int j = 0; j < 4; j++) {
                    const int i = lane + 32*j;
                    if (i > k) {
                        float* row = A + perm[i]*LDA;
                        const float m = row[k] * inv;
                        row[k] = m;
                        #pragma unroll
                        for (int c = 0; c < PB; c++)
                            if (c > kk) row[kp + c] -= m * prow[c];
                    }
                }
                __syncwarp();
            }
        }
        __syncthreads();   // panel (L factors, U rows, perm) visible to all warps

        // ---- trailing update: A[i, c>=pe] -= L[i, kp:pe] @ U[kp:pe, c>=pe] ----
        const int pe = kp + PB;
        if (pe < NF) {
            // Build U panel via forward substitution (TRSM), in registers.
            // Raw pivot rows only carry the panel-internal updates; trailing
            // columns need  U[k2][c] = Araw[k2][c] - sum_{j2<k2} Lp[k2][j2]*U[j2][c].
            float u[PB][4];
            #pragma unroll
            for (int k2 = 0; k2 < PB; k2++) {
                const float* ur = A + perm[kp + k2]*LDA;
                float lp[PB];
                #pragma unroll
                for (int j2 = 0; j2 < PB; j2++)
                    if (j2 < k2) lp[j2] = ur[kp + j2];    // panel multipliers (broadcast)
                #pragma unroll
                for (int j = 0; j < 4; j++) {
                    float val = ur[lane + 32*j];
                    #pragma unroll
                    for (int j2 = 0; j2 < PB; j2++)
                        if (j2 < k2) val -= lp[j2] * u[j2][j];
                    u[k2][j] = val;
                }
            }
            for (int i = pe + wid; i < NF; i += 8) {
                float* row = A + perm[i]*LDA;
                float l[PB];
                #pragma unroll
                for (int k2 = 0; k2 < PB; k2++) l[k2] = row[kp + k2];  // broadcast
                #pragma unroll
                for (int j = 0; j < 4; j++) {
                    const int c = lane + 32*j;
                    if (c >= pe) {
                        float a = row[c];
                        #pragma unroll
                        for (int k2 = 0; k2 < PB; k2++) a -= l[k2] * u[k2][j];
                        row[c] = a;
                    }
                }
            }
        }
        __syncthreads();   // trailing block updated before next panel's pivoting
    }

    // ---------- 5. combine & write real part of log psi ----------
    if (tid == 0) {
        float J = 0.0f;
        #pragma unroll
        for (int w = 0; w < 8; w++) J += sJ[w];
        out[s] = logabs + J;
    }
}

extern "C" void kernel_launch(void* const* d_in, const int* in_sizes, int n_in,
                              void* d_out, int out_size)
{
    // Identify inputs by element count (robust to metadata ordering):
    const float* n = nullptr;
    const float* M = nullptr;
    const float* W = nullptr;
    const float* b = nullptr;
    for (int i = 0; i < n_in; i++) {
        switch (in_sizes[i]) {
            case NB * NO:  n = (const float*)d_in[i]; break;
            case NO * NF:  M = (const float*)d_in[i]; break;
            case NO * HID: W = (const float*)d_in[i]; break;
            case HID:      b = (const float*)d_in[i]; break;
            default: break;
        }
    }
    float* out = (float*)d_out;   // (4096,) float32: real part of log psi

    cudaFuncSetAttribute(lnjs_kernel,
                         cudaFuncAttributeMaxDynamicSharedMemorySize,
                         SMEM_BYTES);

    lnjs_kernel<<<NB, NTHR, SMEM_BYTES>>>(n, M, W, b, out);
}

// round 7
// speedup vs baseline: 1.6330x; 1.1999x over previous
#include <cuda_runtime.h>
#include <cstdint>

#define NB    4096     // batch
#define NO    256      // orbitals
#define NF    128      // fermions
#define HID   512      // hidden
#define LDA   129      // padded row stride (129 mod 32 == 1)
#define NTHR  256
#define PB    8        // LU panel width
#define NPAN  (NF/PB)  // 16 panels

// Shared layout (floats): A | idx | perm | pcopy | wcnt(8) | sJ(8)
#define SMEM_FLOATS (NF*LDA + NF + NF + NF + 8 + 8)
#define SMEM_BYTES  (SMEM_FLOATS * 4)

// Warp-synchronous panel factorization (executed by warp 0 only).
// Factors panel columns [kp, kp+PB) over logical rows >= kp, smem-resident,
// virtual pivoting via perm. Accumulates log|pivot| into logabs (lane 0).
__device__ __forceinline__ void factor_panel(float* __restrict__ A,
                                             int*   __restrict__ perm,
                                             int kp, int lane, float& logabs)
{
    #pragma unroll
    for (int kk = 0; kk < PB; kk++) {
        const int k = kp + kk;
        // pivot search over logical rows >= k
        float v = -1.0f; int vi = k;
        #pragma unroll
        for (int j = 0; j < 4; j++) {
            const int i = lane + 32*j;
            if (i >= k) {
                const float a = fabsf(A[perm[i]*LDA + k]);
                if (a > v) { v = a; vi = i; }
            }
        }
        #pragma unroll
        for (int o = 16; o; o >>= 1) {
            const float ov = __shfl_xor_sync(0xffffffffu, v,  o);
            const int   oi = __shfl_xor_sync(0xffffffffu, vi, o);
            if (ov > v) { v = ov; vi = oi; }
        }
        int pk = 0; float inv = 0.0f;
        if (lane == 0) {
            if (vi != k) { int t = perm[k]; perm[k] = perm[vi]; perm[vi] = t; }
            pk = perm[k];
            const float piv = A[pk*LDA + k];
            logabs += __logf(fabsf(piv));
            inv = 1.0f / piv;
        }
        __syncwarp();
        pk  = __shfl_sync(0xffffffffu, pk,  0);
        inv = __shfl_sync(0xffffffffu, inv, 0);

        const float* prow = A + pk*LDA + kp;
        #pragma unroll
        for (int j = 0; j < 4; j++) {
            const int i = lane + 32*j;
            if (i > k) {
                float* row = A + perm[i]*LDA;
                const float m = row[k] * inv;
                row[k] = m;
                #pragma unroll
                for (int c = 0; c < PB; c++)
                    if (c > kk) row[kp + c] -= m * prow[c];
            }
        }
        __syncwarp();
    }
}

__global__ void __launch_bounds__(NTHR, 3)
lnjs_kernel(const float* __restrict__ n_in,
            const float* __restrict__ M_in,
            const float* __restrict__ W_in,
            const float* __restrict__ b_in,
            float* __restrict__ out)
{
    extern __shared__ float sm[];
    float* A     = sm;
    int*   idx   = (int*)(sm + NF*LDA);
    int*   perm  = idx + NF;
    int*   pcopy = perm + NF;
    int*   wcnt  = pcopy + NF;
    float* sJ    = (float*)(wcnt + 8);

    const int s    = blockIdx.x;
    const int tid  = threadIdx.x;
    const int lane = tid & 31;
    const int wid  = tid >> 5;

    // ---------- 1. occupied indices via ballot prefix (NO == NTHR == 256) ----------
    const float nv = n_in[s*NO + tid];
    const bool occ = nv > 0.5f;
    const unsigned mask = __ballot_sync(0xffffffffu, occ);
    const int rank = __popc(mask & ((1u << lane) - 1u));
    if (lane == 0) wcnt[wid] = __popc(mask);
    __syncthreads();
    {
        int off = 0;
        #pragma unroll
        for (int w = 0; w < 8; w++) if (w < wid) off += wcnt[w];
        if (occ) idx[off + rank] = tid;
    }
    if (tid < NF) perm[tid] = tid;
    __syncthreads();

    // ---------- 2. Jastrow: each thread owns hidden units tid and tid+256 ----------
    float acc0 = b_in[tid];
    float acc1 = b_in[tid + 256];
    #pragma unroll 4
    for (int i = 0; i < NF; i++) {
        const float* wr = W_in + (size_t)idx[i] * HID;
        acc0 += wr[tid];
        acc1 += wr[tid + 256];
    }
    float jl = tanhf(acc0) + tanhf(acc1);
    #pragma unroll
    for (int o = 16; o; o >>= 1) jl += __shfl_xor_sync(0xffffffffu, jl, o);
    if (lane == 0) sJ[wid] = jl;

    // ---------- 3. load Slater matrix A = M[idx] into smem ----------
    #pragma unroll
    for (int e = tid; e < NF*NF; e += NTHR) {
        const int r = e >> 7;
        const int c = e & 127;
        A[r*LDA + c] = M_in[(size_t)idx[r] * NF + c];
    }
    __syncthreads();

    // ---------- 4. blocked LU with partial pivoting + lookahead-1 ----------
    float logabs = 0.0f;   // warp 0 lane 0 accumulates

    // prologue: factor panel 0 (exposed; all later panels hidden under updates)
    if (wid == 0) factor_panel(A, perm, 0, lane, logabs);
    __syncthreads();

    for (int p = 0; p < NPAN - 1; p++) {
        const int kp = p * PB;
        const int pe = kp + PB;

        // ======== phase A (all 8 warps) ========
        // a) snapshot perm[pe..NF) for phase-B workers (warp 0 mutates perm in B)
        if (pe + tid < NF) pcopy[pe + tid] = perm[pe + tid];

        // b) update next panel's 8-column strip: rows logical >= pe, cols [pe,pe+8)
        {
            const int c0 = lane & 7;        // column offset within strip
            const int rs = lane >> 3;       // row sub-index (0..3)
            // per-lane TRSM: u8[k2] = U[kp+k2][pe+c0]
            float u8[PB];
            #pragma unroll
            for (int k2 = 0; k2 < PB; k2++) {
                const float* ur = A + perm[kp + k2]*LDA;
                float val = ur[pe + c0];
                #pragma unroll
                for (int j2 = 0; j2 < PB; j2++)
                    if (j2 < k2) val -= ur[kp + j2] * u8[j2];
                u8[k2] = val;
            }
            for (int i = pe + (wid << 2) + rs; i < NF; i += 32) {
                float* row = A + perm[i]*LDA;
                float a = row[pe + c0];
                #pragma unroll
                for (int k2 = 0; k2 < PB; k2++)
                    a -= row[kp + k2] * u8[k2];
                row[pe + c0] = a;
            }
        }
        __syncthreads();

        // ======== phase B (concurrent, disjoint columns) ========
        if (wid == 0) {
            // factor next panel: cols [pe, pe+8), rows logical >= pe
            factor_panel(A, perm, pe, lane, logabs);
        } else {
            // wide trailing update: cols >= pe+8, rows logical >= pe (via snapshot)
            // build U panel via TRSM in registers (pivot rows logical < pe: stable)
            float u[PB][4];
            #pragma unroll
            for (int k2 = 0; k2 < PB; k2++) {
                const float* ur = A + perm[kp + k2]*LDA;
                float lp[PB];
                #pragma unroll
                for (int j2 = 0; j2 < PB; j2++)
                    if (j2 < k2) lp[j2] = ur[kp + j2];
                #pragma unroll
                for (int j = 0; j < 4; j++) {
                    float val = ur[lane + 32*j];
                    #pragma unroll
                    for (int j2 = 0; j2 < PB; j2++)
                        if (j2 < k2) val -= lp[j2] * u[j2][j];
                    u[k2][j] = val;
                }
            }
            for (int i = pe + (wid - 1); i < NF; i += 7) {
                float* row = A + pcopy[i]*LDA;
                float l[PB];
                #pragma unroll
                for (int k2 = 0; k2 < PB; k2++) l[k2] = row[kp + k2];
                #pragma unroll
                for (int j = 0; j < 4; j++) {
                    const int c = lane + 32*j;
                    if (c >= pe + PB) {
                        float a = row[c];
                        #pragma unroll
                        for (int k2 = 0; k2 < PB; k2++) a -= l[k2] * u[k2][j];
                        row[c] = a;
                    }
                }
            }
        }
        __syncthreads();
    }

    // ---------- 5. combine & write real part of log psi ----------
    if (tid == 0) {
        float J = 0.0f;
        #pragma unroll
        for (int w = 0; w < 8; w++) J += sJ[w];
        out[s] = logabs + J;
    }
}

extern "C" void kernel_launch(void* const* d_in, const int* in_sizes, int n_in,
                              void* d_out, int out_size)
{
    // Identify inputs by element count (robust to metadata ordering):
    const float* n = nullptr;
    const float* M = nullptr;
    const float* W = nullptr;
    const float* b = nullptr;
    for (int i = 0; i < n_in; i++) {
        switch (in_sizes[i]) {
            case NB * NO:  n = (const float*)d_in[i]; break;
            case NO * NF:  M = (const float*)d_in[i]; break;
            case NO * HID: W = (const float*)d_in[i]; break;
            case HID:      b = (const float*)d_in[i]; break;
            default: break;
        }
    }
    float* out = (float*)d_out;   // (4096,) float32: real part of log psi

    cudaFuncSetAttribute(lnjs_kernel,
                         cudaFuncAttributeMaxDynamicSharedMemorySize,
                         SMEM_BYTES);

    lnjs_kernel<<<NB, NTHR, SMEM_BYTES>>>(n, M, W, b, out);
}